// round 7
// baseline (speedup 1.0000x reference)
#include <cuda_runtime.h>

#define MAXN  100000
#define MAXE  3200000
#define HD    64
#define NG    512
#define NC    10
#define SCANB 1024
#define MAXBLK 128   // ceil(MAXN/SCANB) = 98

// ---------------- scratch (device globals) ----------------------------------
__device__ int    g_deg[MAXN];
__device__ int    g_cur[MAXN];
__device__ int    g_off[MAXN + 1];
__device__ int    g_blksum[MAXBLK];
__device__ int    g_blkoff[MAXBLK];
__device__ float  g_dis[MAXN];              // 1/sqrt(deg+1)
__device__ int    g_srcs[MAXE];             // src ids, CSR-sorted by dst
__device__ float4 g_bufA[MAXN * HD / 4];
__device__ float4 g_bufB[MAXN * HD / 4];
__device__ float4 g_pool[NG * HD / 4];
__device__ float  g_cnt [NG];

// ---------------- helpers ---------------------------------------------------
__device__ __forceinline__ void red_add_v4(float4* p, float4 v) {
    asm volatile("red.global.add.v4.f32 [%0], {%1,%2,%3,%4};"
                 :: "l"(p), "f"(v.x), "f"(v.y), "f"(v.z), "f"(v.w)
                 : "memory");
}

// packed fp32x2 FMA: d = a*b + c (elementwise on 2 packed floats)
__device__ __forceinline__ unsigned long long fma2(unsigned long long a,
                                                   unsigned long long b,
                                                   unsigned long long c) {
    unsigned long long d;
    asm("fma.rn.f32x2 %0, %1, %2, %3;" : "=l"(d) : "l"(a), "l"(b), "l"(c));
    return d;
}

// ---------------- CSR build --------------------------------------------------
__global__ void deg_count(const int* __restrict__ dst, int* __restrict__ deg,
                          int E) {
    int e = blockIdx.x * blockDim.x + threadIdx.x;
    if (e < E) atomicAdd(&deg[dst[e]], 1);
}

__global__ void node_norms(const int* __restrict__ deg, float* __restrict__ dis,
                           int N) {
    int i = blockIdx.x * blockDim.x + threadIdx.x;
    if (i < N) dis[i] = rsqrtf((float)deg[i] + 1.0f);
}

// ---- 3-phase parallel exclusive scan of deg[0..N) into off[0..N] ----
__global__ void scan_p1_reduce(const int* __restrict__ deg,
                               int* __restrict__ blksum, int N) {
    __shared__ int ws[32];
    int i = blockIdx.x * SCANB + threadIdx.x;
    int v = (i < N) ? deg[i] : 0;
    int lane = threadIdx.x & 31, wid = threadIdx.x >> 5;
#pragma unroll
    for (int o = 16; o > 0; o >>= 1) v += __shfl_down_sync(~0u, v, o);
    if (lane == 0) ws[wid] = v;
    __syncthreads();
    if (wid == 0) {
        int t = ws[lane];
#pragma unroll
        for (int o = 16; o > 0; o >>= 1) t += __shfl_down_sync(~0u, t, o);
        if (lane == 0) blksum[blockIdx.x] = t;
    }
}

__global__ void scan_p2_blk(const int* __restrict__ blksum,
                            int* __restrict__ blkoff,
                            int* __restrict__ off, int nblk, int N) {
    __shared__ int s[MAXBLK];
    int t = threadIdx.x;                        // MAXBLK threads
    s[t] = (t < nblk) ? blksum[t] : 0;
    __syncthreads();
#pragma unroll
    for (int o = 1; o < MAXBLK; o <<= 1) {      // Hillis-Steele inclusive
        int v = (t >= o) ? s[t - o] : 0;
        __syncthreads();
        s[t] += v;
        __syncthreads();
    }
    if (t < nblk) blkoff[t] = s[t] - blksum[t]; // exclusive
    if (t == nblk - 1) off[N] = s[t];           // total
}

__global__ void scan_p3_scanadd(const int* __restrict__ deg,
                                const int* __restrict__ blkoff,
                                int* __restrict__ off, int N) {
    __shared__ int wpre[32];
    int i = blockIdx.x * SCANB + threadIdx.x;
    int v = (i < N) ? deg[i] : 0;
    int lane = threadIdx.x & 31, wid = threadIdx.x >> 5;
    int incl = v;
#pragma unroll
    for (int o = 1; o < 32; o <<= 1) {
        int t = __shfl_up_sync(~0u, incl, o);
        if (lane >= o) incl += t;
    }
    if (lane == 31) wpre[wid] = incl;
    __syncthreads();
    if (wid == 0) {
        int w = wpre[lane];
        int wincl = w;
#pragma unroll
        for (int o = 1; o < 32; o <<= 1) {
            int t = __shfl_up_sync(~0u, wincl, o);
            if (lane >= o) wincl += t;
        }
        wpre[lane] = wincl - w;
    }
    __syncthreads();
    if (i < N) off[i] = blkoff[blockIdx.x] + wpre[wid] + incl - v;
}

// cur[] preloaded with off[]; atomic return carries the base directly.
__global__ void permute_edges(const int* __restrict__ src,
                              const int* __restrict__ dst,
                              int* __restrict__ cur,
                              int* __restrict__ srcs, int E) {
    int e = blockIdx.x * blockDim.x + threadIdx.x;
    if (e >= E) return;
    int s = src[e], d = dst[e];
    int p = atomicAdd(&cur[d], 1);
    srcs[p] = s;
}

// ---------------- GEMM (FFMA2): out[N,64] = in[N,K] @ W[K,64] ----------------
// 64x64 block tile, 256 threads, 4x4 register tile per thread, packed f32x2.
// sx_dup: k-major x tile with each element duplicated -> free (a,a) pairs.
#define SXD_STRIDE 132
template <int K>
__global__ __launch_bounds__(256)
void gemm_tile(const float* __restrict__ in, const float* __restrict__ W,
               float* __restrict__ out, int N) {
    __shared__ float sx_dup[32 * SXD_STRIDE];   // [k][2*row(+dup)]
    __shared__ float sw[32 * 64];               // [k][col]
    int tid = threadIdx.x;
    int tx = tid & 15, ty = tid >> 4;
    int row0 = blockIdx.x * 64;
    unsigned long long acc[4][2] = {};          // [row][colpair], packed f32x2
    for (int kc = 0; kc < K; kc += 32) {
#pragma unroll
        for (int i = 0; i < 2; i++) {           // x chunk: 64 rows x 32 k
            int t = tid + i * 256;              // 512 float4 slots
            int r = t >> 3, c4 = t & 7;
            int grow = row0 + r;
            float4 v = make_float4(0.f, 0.f, 0.f, 0.f);
            if (grow < N)
                v = *(const float4*)&in[(size_t)grow * K + kc + c4 * 4];
            float vv[4] = {v.x, v.y, v.z, v.w};
#pragma unroll
            for (int j = 0; j < 4; j++) {       // duplicate into k-major tile
                float2 d2 = make_float2(vv[j], vv[j]);
                *(float2*)&sx_dup[(c4 * 4 + j) * SXD_STRIDE + 2 * r] = d2;
            }
        }
#pragma unroll
        for (int i = 0; i < 2; i++) {           // W chunk: 32 k x 64 cols
            int t = tid + i * 256;
            int k = t >> 4, c4 = t & 15;
            *(float4*)&sw[k * 64 + c4 * 4] =
                *(const float4*)&W[(size_t)(kc + k) * 64 + c4 * 4];
        }
        __syncthreads();
#pragma unroll
        for (int k = 0; k < 32; k++) {
            float4 bv = *(float4*)&sw[k * 64 + tx * 4];
            float4 a01 = *(float4*)&sx_dup[k * SXD_STRIDE + ty * 8];      // (a0,a0,a1,a1)
            float4 a23 = *(float4*)&sx_dup[k * SXD_STRIDE + ty * 8 + 4];  // (a2,a2,a3,a3)
            unsigned long long b01 = *(unsigned long long*)&bv.x;
            unsigned long long b23 = *(unsigned long long*)&bv.z;
            unsigned long long ap0 = *(unsigned long long*)&a01.x;
            unsigned long long ap1 = *(unsigned long long*)&a01.z;
            unsigned long long ap2 = *(unsigned long long*)&a23.x;
            unsigned long long ap3 = *(unsigned long long*)&a23.z;
            acc[0][0] = fma2(ap0, b01, acc[0][0]);
            acc[0][1] = fma2(ap0, b23, acc[0][1]);
            acc[1][0] = fma2(ap1, b01, acc[1][0]);
            acc[1][1] = fma2(ap1, b23, acc[1][1]);
            acc[2][0] = fma2(ap2, b01, acc[2][0]);
            acc[2][1] = fma2(ap2, b23, acc[2][1]);
            acc[3][0] = fma2(ap3, b01, acc[3][0]);
            acc[3][1] = fma2(ap3, b23, acc[3][1]);
        }
        __syncthreads();
    }
#pragma unroll
    for (int i = 0; i < 4; i++) {
        int grow = row0 + ty * 4 + i;
        if (grow < N) {
            float2 p0 = *(float2*)&acc[i][0];
            float2 p1 = *(float2*)&acc[i][1];
            *(float4*)&out[(size_t)grow * 64 + tx * 4] =
                make_float4(p0.x, p0.y, p1.x, p1.y);
        }
    }
}

// ---------------- fused CSR gather + self-loop + bias + relu (+pool) ---------
// one warp per dst node; two 16-lane halves each own one edge; lane owns
// 4 consecutive feature columns (float4).
__global__ __launch_bounds__(256)
void gather_csr(const int* __restrict__ off, const int* __restrict__ srcs,
                const float* __restrict__ dis, const float* __restrict__ hin,
                float* __restrict__ hout, const float* __restrict__ bias,
                const int* __restrict__ batch, float4* __restrict__ pool4,
                float* __restrict__ cnt, int N, int do_relu, int do_pool) {
    int w = (blockIdx.x * blockDim.x + threadIdx.x) >> 5;
    int lane = threadIdx.x & 31;
    if (w >= N) return;
    int half = lane >> 4;
    int l16  = lane & 15;
    const float4* h4 = (const float4*)hin;
    int s = off[w], e = off[w + 1];
    float dw = dis[w];
    float4 acc = make_float4(0.f, 0.f, 0.f, 0.f);
    int i = s + half;
    for (; i + 2 < e; i += 4) {                 // 2 edges per half per iter
        int u0 = __ldg(&srcs[i]);
        int u1 = __ldg(&srcs[i + 2]);
        float n0 = __ldg(&dis[u0]) * dw;
        float n1 = __ldg(&dis[u1]) * dw;
        float4 v0 = h4[(size_t)u0 * 16 + l16];
        float4 v1 = h4[(size_t)u1 * 16 + l16];
        acc.x = fmaf(v0.x, n0, acc.x); acc.y = fmaf(v0.y, n0, acc.y);
        acc.z = fmaf(v0.z, n0, acc.z); acc.w = fmaf(v0.w, n0, acc.w);
        acc.x = fmaf(v1.x, n1, acc.x); acc.y = fmaf(v1.y, n1, acc.y);
        acc.z = fmaf(v1.z, n1, acc.z); acc.w = fmaf(v1.w, n1, acc.w);
    }
    for (; i < e; i += 2) {                     // at most one per half
        int u = __ldg(&srcs[i]);
        float n = __ldg(&dis[u]) * dw;
        float4 v = h4[(size_t)u * 16 + l16];
        acc.x = fmaf(v.x, n, acc.x); acc.y = fmaf(v.y, n, acc.y);
        acc.z = fmaf(v.z, n, acc.z); acc.w = fmaf(v.w, n, acc.w);
    }
    // combine the two halves (lane l gets lane l+16's partial)
    acc.x += __shfl_down_sync(~0u, acc.x, 16);
    acc.y += __shfl_down_sync(~0u, acc.y, 16);
    acc.z += __shfl_down_sync(~0u, acc.z, 16);
    acc.w += __shfl_down_sync(~0u, acc.w, 16);
    if (half == 0) {
        float sn = dw * dw;
        float4 self = h4[(size_t)w * 16 + l16];
        float4 b = ((const float4*)bias)[l16];
        acc.x = fmaf(self.x, sn, acc.x) + b.x;
        acc.y = fmaf(self.y, sn, acc.y) + b.y;
        acc.z = fmaf(self.z, sn, acc.z) + b.z;
        acc.w = fmaf(self.w, sn, acc.w) + b.w;
        if (do_relu) {
            acc.x = fmaxf(acc.x, 0.f); acc.y = fmaxf(acc.y, 0.f);
            acc.z = fmaxf(acc.z, 0.f); acc.w = fmaxf(acc.w, 0.f);
        }
        ((float4*)hout)[(size_t)w * 16 + l16] = acc;
        if (do_pool) {
            int g = batch[w];
            red_add_v4(&pool4[(size_t)g * 16 + l16], acc);
            if (l16 == 0) atomicAdd(&cnt[g], 1.0f);
        }
    }
}

// ---------------- FC -----------------------------------------------------
__global__ void fc_kernel(const float* __restrict__ pool,
                          const float* __restrict__ cnt,
                          const float* __restrict__ Wfc,
                          const float* __restrict__ bfc,
                          float* __restrict__ out) {
    int b = blockIdx.x;
    int t = threadIdx.x;           // 64 threads
    __shared__ float p[HD];
    float inv = 1.0f / fmaxf(cnt[b], 1.0f);
    p[t] = pool[b * HD + t] * inv;
    __syncthreads();
    if (t < NC) {
        float acc = bfc[t];
#pragma unroll
        for (int h = 0; h < HD; h++)
            acc = fmaf(p[h], Wfc[h * NC + t], acc);
        out[b * NC + t] = acc;
    }
}

// ---------------- launch -----------------------------------------------------
extern "C" void kernel_launch(void* const* d_in, const int* in_sizes, int n_in,
                              void* d_out, int out_size) {
    const float* x     = (const float*)d_in[0];
    const int*   ei    = (const int*)d_in[1];     // int32 (JAX x64 disabled)
    const int*   batch = (const int*)d_in[2];
    const float* W1    = (const float*)d_in[3];
    const float* b1    = (const float*)d_in[4];
    const float* W2    = (const float*)d_in[5];
    const float* b2    = (const float*)d_in[6];
    const float* W3    = (const float*)d_in[7];
    const float* b3    = (const float*)d_in[8];
    const float* Wfc   = (const float*)d_in[9];
    const float* bfc   = (const float*)d_in[10];
    float*       out   = (float*)d_out;

    int N = in_sizes[0] / 128;
    int E = in_sizes[1] / 2;
    int B = out_size / NC;

    const int* src = ei;
    const int* dst = ei + E;

    void *p_deg, *p_cur, *p_off, *p_bs, *p_bo, *p_dis, *p_srcs,
         *p_A, *p_B, *p_pool, *p_cnt;
    cudaGetSymbolAddress(&p_deg, g_deg);
    cudaGetSymbolAddress(&p_cur, g_cur);
    cudaGetSymbolAddress(&p_off, g_off);
    cudaGetSymbolAddress(&p_bs, g_blksum);
    cudaGetSymbolAddress(&p_bo, g_blkoff);
    cudaGetSymbolAddress(&p_dis, g_dis);
    cudaGetSymbolAddress(&p_srcs, g_srcs);
    cudaGetSymbolAddress(&p_A, g_bufA);
    cudaGetSymbolAddress(&p_B, g_bufB);
    cudaGetSymbolAddress(&p_pool, g_pool);
    cudaGetSymbolAddress(&p_cnt, g_cnt);

    int*    deg   = (int*)p_deg;
    int*    cur   = (int*)p_cur;
    int*    off   = (int*)p_off;
    int*    blks  = (int*)p_bs;
    int*    blko  = (int*)p_bo;
    float*  dis   = (float*)p_dis;
    int*    srcs  = (int*)p_srcs;
    float*  A     = (float*)p_A;
    float*  Bb    = (float*)p_B;
    float4* pool4 = (float4*)p_pool;
    float*  pool  = (float*)p_pool;
    float*  cnt   = (float*)p_cnt;

    const int T = 256;
    int gEdge = (E + T - 1) / T;
    int gNode = (N + T - 1) / T;
    int gWarp = (int)(((long long)N * 32 + T - 1) / T);
    int gGemm = (N + 63) / 64;
    int nblk  = (N + SCANB - 1) / SCANB;

    // ---- CSR build + norms ----
    cudaMemsetAsync(deg, 0, (size_t)N * sizeof(int));
    deg_count<<<gEdge, T>>>(dst, deg, E);
    node_norms<<<gNode, T>>>(deg, dis, N);
    scan_p1_reduce<<<nblk, SCANB>>>(deg, blks, N);
    scan_p2_blk<<<1, MAXBLK>>>(blks, blko, off, nblk, N);
    scan_p3_scanadd<<<nblk, SCANB>>>(deg, blko, off, N);
    cudaMemcpyAsync(cur, off, (size_t)N * sizeof(int), cudaMemcpyDeviceToDevice);
    permute_edges<<<gEdge, T>>>(src, dst, cur, srcs, E);

    // ---- pool buffers (zero early; written only by gather3) ----
    cudaMemsetAsync(pool4, 0, (size_t)B * HD * sizeof(float));
    cudaMemsetAsync(cnt, 0, (size_t)B * sizeof(float));

    // ---- layer 1: x(128) -> A -> B ----
    gemm_tile<128><<<gGemm, T>>>(x, W1, A, N);
    gather_csr<<<gWarp, T>>>(off, srcs, dis, A, Bb, b1, batch, pool4, cnt, N, 1, 0);

    // ---- layer 2: B -> A -> B ----
    gemm_tile<64><<<gGemm, T>>>(Bb, W2, A, N);
    gather_csr<<<gWarp, T>>>(off, srcs, dis, A, Bb, b2, batch, pool4, cnt, N, 1, 0);

    // ---- layer 3: B -> A -> B (+ fused pooling) ----
    gemm_tile<64><<<gGemm, T>>>(Bb, W3, A, N);
    gather_csr<<<gWarp, T>>>(off, srcs, dis, A, Bb, b3, batch, pool4, cnt, N, 0, 1);

    // ---- fc ----
    fc_kernel<<<B, HD>>>(pool, cnt, Wfc, bfc, out);
}

// round 8
// speedup vs baseline: 1.1384x; 1.1384x over previous
#include <cuda_runtime.h>

#define MAXN  100000
#define MAXE  3200000
#define HD    64
#define NG    512
#define NC    10
#define SCANB 1024
#define MAXBLK 128   // ceil(MAXN/SCANB) = 98

// ---------------- scratch (device globals) ----------------------------------
__device__ int    g_deg[MAXN];
__device__ int    g_cur[MAXN];
__device__ int    g_off[MAXN + 1];
__device__ int    g_blksum[MAXBLK];
__device__ int    g_blkoff[MAXBLK];
__device__ float  g_dis[MAXN];              // 1/sqrt(deg+1)
__device__ int    g_srcs[MAXE];             // src ids, CSR-sorted by dst
__device__ float4 g_bufA[MAXN * HD / 4];
__device__ float4 g_bufB[MAXN * HD / 4];
__device__ float4 g_pool[NG * HD / 4];
__device__ float  g_cnt [NG];

// ---------------- helpers ---------------------------------------------------
__device__ __forceinline__ void red_add_v4(float4* p, float4 v) {
    asm volatile("red.global.add.v4.f32 [%0], {%1,%2,%3,%4};"
                 :: "l"(p), "f"(v.x), "f"(v.y), "f"(v.z), "f"(v.w)
                 : "memory");
}

// ---------------- CSR build --------------------------------------------------
__global__ void deg_count(const int* __restrict__ dst, int* __restrict__ deg,
                          int E) {
    int e = blockIdx.x * blockDim.x + threadIdx.x;
    if (e < E) atomicAdd(&deg[dst[e]], 1);
}

__global__ void node_norms(const int* __restrict__ deg, float* __restrict__ dis,
                           int N) {
    int i = blockIdx.x * blockDim.x + threadIdx.x;
    if (i < N) dis[i] = rsqrtf((float)deg[i] + 1.0f);
}

// ---- 3-phase parallel exclusive scan of deg[0..N) into off[0..N] ----
__global__ void scan_p1_reduce(const int* __restrict__ deg,
                               int* __restrict__ blksum, int N) {
    __shared__ int ws[32];
    int i = blockIdx.x * SCANB + threadIdx.x;
    int v = (i < N) ? deg[i] : 0;
    int lane = threadIdx.x & 31, wid = threadIdx.x >> 5;
#pragma unroll
    for (int o = 16; o > 0; o >>= 1) v += __shfl_down_sync(~0u, v, o);
    if (lane == 0) ws[wid] = v;
    __syncthreads();
    if (wid == 0) {
        int t = ws[lane];
#pragma unroll
        for (int o = 16; o > 0; o >>= 1) t += __shfl_down_sync(~0u, t, o);
        if (lane == 0) blksum[blockIdx.x] = t;
    }
}

__global__ void scan_p2_blk(const int* __restrict__ blksum,
                            int* __restrict__ blkoff,
                            int* __restrict__ off, int nblk, int N) {
    __shared__ int s[MAXBLK];
    int t = threadIdx.x;                        // MAXBLK threads
    s[t] = (t < nblk) ? blksum[t] : 0;
    __syncthreads();
#pragma unroll
    for (int o = 1; o < MAXBLK; o <<= 1) {      // Hillis-Steele inclusive
        int v = (t >= o) ? s[t - o] : 0;
        __syncthreads();
        s[t] += v;
        __syncthreads();
    }
    if (t < nblk) blkoff[t] = s[t] - blksum[t]; // exclusive
    if (t == nblk - 1) off[N] = s[t];           // total
}

// writes both off[] and cur[] (cur consumed/destroyed by permute)
__global__ void scan_p3_scanadd(const int* __restrict__ deg,
                                const int* __restrict__ blkoff,
                                int* __restrict__ off,
                                int* __restrict__ cur, int N) {
    __shared__ int wpre[32];
    int i = blockIdx.x * SCANB + threadIdx.x;
    int v = (i < N) ? deg[i] : 0;
    int lane = threadIdx.x & 31, wid = threadIdx.x >> 5;
    int incl = v;
#pragma unroll
    for (int o = 1; o < 32; o <<= 1) {
        int t = __shfl_up_sync(~0u, incl, o);
        if (lane >= o) incl += t;
    }
    if (lane == 31) wpre[wid] = incl;
    __syncthreads();
    if (wid == 0) {
        int w = wpre[lane];
        int wincl = w;
#pragma unroll
        for (int o = 1; o < 32; o <<= 1) {
            int t = __shfl_up_sync(~0u, wincl, o);
            if (lane >= o) wincl += t;
        }
        wpre[lane] = wincl - w;
    }
    __syncthreads();
    if (i < N) {
        int o = blkoff[blockIdx.x] + wpre[wid] + incl - v;
        off[i] = o;
        cur[i] = o;
    }
}

// cur[] preloaded with off[]; atomic return carries the base directly.
__global__ void permute_edges(const int* __restrict__ src,
                              const int* __restrict__ dst,
                              int* __restrict__ cur,
                              int* __restrict__ srcs, int E) {
    int e = blockIdx.x * blockDim.x + threadIdx.x;
    if (e >= E) return;
    int s = src[e], d = dst[e];
    int p = atomicAdd(&cur[d], 1);
    srcs[p] = s;
}

// ---------------- GEMM: out[N,64] = in[N,K] @ W[K,64]  (R6 version) ----------
template <int K>
__global__ __launch_bounds__(256)
void gemm_tile(const float* __restrict__ in, const float* __restrict__ W,
               float* __restrict__ out, int N) {
    __shared__ float sx[64 * 36];
    __shared__ float sw[32 * 64];
    int tid = threadIdx.x;
    int tx = tid & 15, ty = tid >> 4;
    int row0 = blockIdx.x * 64;
    float acc[4][4] = {};
    for (int kc = 0; kc < K; kc += 32) {
#pragma unroll
        for (int i = 0; i < 2; i++) {
            int t = tid + i * 256;
            int r = t >> 3, c4 = t & 7;
            int grow = row0 + r;
            float4 v = make_float4(0.f, 0.f, 0.f, 0.f);
            if (grow < N)
                v = *(const float4*)&in[(size_t)grow * K + kc + c4 * 4];
            *(float4*)&sx[r * 36 + c4 * 4] = v;
        }
#pragma unroll
        for (int i = 0; i < 2; i++) {
            int t = tid + i * 256;
            int k = t >> 4, c4 = t & 15;
            *(float4*)&sw[k * 64 + c4 * 4] =
                *(const float4*)&W[(size_t)(kc + k) * 64 + c4 * 4];
        }
        __syncthreads();
#pragma unroll
        for (int k = 0; k < 32; k++) {
            float4 b = *(float4*)&sw[k * 64 + tx * 4];
            float a0 = sx[(ty * 4 + 0) * 36 + k];
            float a1 = sx[(ty * 4 + 1) * 36 + k];
            float a2 = sx[(ty * 4 + 2) * 36 + k];
            float a3 = sx[(ty * 4 + 3) * 36 + k];
            acc[0][0] = fmaf(a0, b.x, acc[0][0]);
            acc[0][1] = fmaf(a0, b.y, acc[0][1]);
            acc[0][2] = fmaf(a0, b.z, acc[0][2]);
            acc[0][3] = fmaf(a0, b.w, acc[0][3]);
            acc[1][0] = fmaf(a1, b.x, acc[1][0]);
            acc[1][1] = fmaf(a1, b.y, acc[1][1]);
            acc[1][2] = fmaf(a1, b.z, acc[1][2]);
            acc[1][3] = fmaf(a1, b.w, acc[1][3]);
            acc[2][0] = fmaf(a2, b.x, acc[2][0]);
            acc[2][1] = fmaf(a2, b.y, acc[2][1]);
            acc[2][2] = fmaf(a2, b.z, acc[2][2]);
            acc[2][3] = fmaf(a2, b.w, acc[2][3]);
            acc[3][0] = fmaf(a3, b.x, acc[3][0]);
            acc[3][1] = fmaf(a3, b.y, acc[3][1]);
            acc[3][2] = fmaf(a3, b.z, acc[3][2]);
            acc[3][3] = fmaf(a3, b.w, acc[3][3]);
        }
        __syncthreads();
    }
#pragma unroll
    for (int i = 0; i < 4; i++) {
        int grow = row0 + ty * 4 + i;
        if (grow < N)
            *(float4*)&out[(size_t)grow * 64 + tx * 4] =
                make_float4(acc[i][0], acc[i][1], acc[i][2], acc[i][3]);
    }
}

// ---------------- fused CSR gather + self-loop + bias + relu (+pool) ---------
__global__ __launch_bounds__(256)
void gather_csr(const int* __restrict__ off, const int* __restrict__ srcs,
                const float* __restrict__ dis, const float* __restrict__ hin,
                float* __restrict__ hout, const float* __restrict__ bias,
                const int* __restrict__ batch, float4* __restrict__ pool4,
                float* __restrict__ cnt, int N, int do_relu, int do_pool) {
    int w = (blockIdx.x * blockDim.x + threadIdx.x) >> 5;
    int lane = threadIdx.x & 31;
    if (w >= N) return;
    int half = lane >> 4;
    int l16  = lane & 15;
    const float4* h4 = (const float4*)hin;
    int s = off[w], e = off[w + 1];
    float dw = dis[w];
    float4 acc = make_float4(0.f, 0.f, 0.f, 0.f);
    int i = s + half;
    for (; i + 2 < e; i += 4) {                 // 2 edges per half per iter
        int u0 = __ldg(&srcs[i]);
        int u1 = __ldg(&srcs[i + 2]);
        float n0 = __ldg(&dis[u0]) * dw;
        float n1 = __ldg(&dis[u1]) * dw;
        float4 v0 = h4[(size_t)u0 * 16 + l16];
        float4 v1 = h4[(size_t)u1 * 16 + l16];
        acc.x = fmaf(v0.x, n0, acc.x); acc.y = fmaf(v0.y, n0, acc.y);
        acc.z = fmaf(v0.z, n0, acc.z); acc.w = fmaf(v0.w, n0, acc.w);
        acc.x = fmaf(v1.x, n1, acc.x); acc.y = fmaf(v1.y, n1, acc.y);
        acc.z = fmaf(v1.z, n1, acc.z); acc.w = fmaf(v1.w, n1, acc.w);
    }
    for (; i < e; i += 2) {                     // at most one per half
        int u = __ldg(&srcs[i]);
        float n = __ldg(&dis[u]) * dw;
        float4 v = h4[(size_t)u * 16 + l16];
        acc.x = fmaf(v.x, n, acc.x); acc.y = fmaf(v.y, n, acc.y);
        acc.z = fmaf(v.z, n, acc.z); acc.w = fmaf(v.w, n, acc.w);
    }
    acc.x += __shfl_down_sync(~0u, acc.x, 16);
    acc.y += __shfl_down_sync(~0u, acc.y, 16);
    acc.z += __shfl_down_sync(~0u, acc.z, 16);
    acc.w += __shfl_down_sync(~0u, acc.w, 16);
    if (half == 0) {
        float sn = dw * dw;
        float4 self = h4[(size_t)w * 16 + l16];
        float4 b = ((const float4*)bias)[l16];
        acc.x = fmaf(self.x, sn, acc.x) + b.x;
        acc.y = fmaf(self.y, sn, acc.y) + b.y;
        acc.z = fmaf(self.z, sn, acc.z) + b.z;
        acc.w = fmaf(self.w, sn, acc.w) + b.w;
        if (do_relu) {
            acc.x = fmaxf(acc.x, 0.f); acc.y = fmaxf(acc.y, 0.f);
            acc.z = fmaxf(acc.z, 0.f); acc.w = fmaxf(acc.w, 0.f);
        }
        ((float4*)hout)[(size_t)w * 16 + l16] = acc;
        if (do_pool) {
            int g = batch[w];
            red_add_v4(&pool4[(size_t)g * 16 + l16], acc);
            if (l16 == 0) atomicAdd(&cnt[g], 1.0f);
        }
    }
}

// ---------------- FC -----------------------------------------------------
__global__ void fc_kernel(const float* __restrict__ pool,
                          const float* __restrict__ cnt,
                          const float* __restrict__ Wfc,
                          const float* __restrict__ bfc,
                          float* __restrict__ out) {
    int b = blockIdx.x;
    int t = threadIdx.x;           // 64 threads
    __shared__ float p[HD];
    float inv = 1.0f / fmaxf(cnt[b], 1.0f);
    p[t] = pool[b * HD + t] * inv;
    __syncthreads();
    if (t < NC) {
        float acc = bfc[t];
#pragma unroll
        for (int h = 0; h < HD; h++)
            acc = fmaf(p[h], Wfc[h * NC + t], acc);
        out[b * NC + t] = acc;
    }
}

// ---------------- launch -----------------------------------------------------
extern "C" void kernel_launch(void* const* d_in, const int* in_sizes, int n_in,
                              void* d_out, int out_size) {
    const float* x     = (const float*)d_in[0];
    const int*   ei    = (const int*)d_in[1];     // int32 (JAX x64 disabled)
    const int*   batch = (const int*)d_in[2];
    const float* W1    = (const float*)d_in[3];
    const float* b1    = (const float*)d_in[4];
    const float* W2    = (const float*)d_in[5];
    const float* b2    = (const float*)d_in[6];
    const float* W3    = (const float*)d_in[7];
    const float* b3    = (const float*)d_in[8];
    const float* Wfc   = (const float*)d_in[9];
    const float* bfc   = (const float*)d_in[10];
    float*       out   = (float*)d_out;

    int N = in_sizes[0] / 128;
    int E = in_sizes[1] / 2;
    int B = out_size / NC;

    const int* src = ei;
    const int* dst = ei + E;

    void *p_deg, *p_cur, *p_off, *p_bs, *p_bo, *p_dis, *p_srcs,
         *p_A, *p_B, *p_pool, *p_cnt;
    cudaGetSymbolAddress(&p_deg, g_deg);
    cudaGetSymbolAddress(&p_cur, g_cur);
    cudaGetSymbolAddress(&p_off, g_off);
    cudaGetSymbolAddress(&p_bs, g_blksum);
    cudaGetSymbolAddress(&p_bo, g_blkoff);
    cudaGetSymbolAddress(&p_dis, g_dis);
    cudaGetSymbolAddress(&p_srcs, g_srcs);
    cudaGetSymbolAddress(&p_A, g_bufA);
    cudaGetSymbolAddress(&p_B, g_bufB);
    cudaGetSymbolAddress(&p_pool, g_pool);
    cudaGetSymbolAddress(&p_cnt, g_cnt);

    int*    deg   = (int*)p_deg;
    int*    cur   = (int*)p_cur;
    int*    off   = (int*)p_off;
    int*    blks  = (int*)p_bs;
    int*    blko  = (int*)p_bo;
    float*  dis   = (float*)p_dis;
    int*    srcs  = (int*)p_srcs;
    float*  A     = (float*)p_A;
    float*  Bb    = (float*)p_B;
    float4* pool4 = (float4*)p_pool;
    float*  pool  = (float*)p_pool;
    float*  cnt   = (float*)p_cnt;

    const int T = 256;
    int gEdge = (E + T - 1) / T;
    int gNode = (N + T - 1) / T;
    int gWarp = (int)(((long long)N * 32 + T - 1) / T);
    int gGemm = (N + 63) / 64;
    int nblk  = (N + SCANB - 1) / SCANB;

    // lazily-created side stream + fork/join events (host-side handles only;
    // identical captured work every call)
    static cudaStream_t s_side = nullptr;
    static cudaEvent_t  ev_fork = nullptr, ev_join = nullptr;
    if (s_side == nullptr) {
        cudaStreamCreateWithFlags(&s_side, cudaStreamNonBlocking);
        cudaEventCreateWithFlags(&ev_fork, cudaEventDisableTiming);
        cudaEventCreateWithFlags(&ev_join, cudaEventDisableTiming);
    }

    // ---- fork: CSR build chain on side stream, GEMM1 on main stream ----
    cudaEventRecord(ev_fork, 0);
    cudaStreamWaitEvent(s_side, ev_fork, 0);

    cudaMemsetAsync(deg, 0, (size_t)N * sizeof(int), s_side);
    deg_count<<<gEdge, T, 0, s_side>>>(dst, deg, E);
    node_norms<<<gNode, T, 0, s_side>>>(deg, dis, N);
    scan_p1_reduce<<<nblk, SCANB, 0, s_side>>>(deg, blks, N);
    scan_p2_blk<<<1, MAXBLK, 0, s_side>>>(blks, blko, off, nblk, N);
    scan_p3_scanadd<<<nblk, SCANB, 0, s_side>>>(deg, blko, off, cur, N);
    permute_edges<<<gEdge, T, 0, s_side>>>(src, dst, cur, srcs, E);
    cudaMemsetAsync(pool4, 0, (size_t)B * HD * sizeof(float), s_side);
    cudaMemsetAsync(cnt, 0, (size_t)B * sizeof(float), s_side);
    cudaEventRecord(ev_join, s_side);

    // main stream: layer-1 GEMM overlaps the CSR build
    gemm_tile<128><<<gGemm, T>>>(x, W1, A, N);

    // join before first gather
    cudaStreamWaitEvent(0, ev_join, 0);

    // ---- layer 1 gather ----
    gather_csr<<<gWarp, T>>>(off, srcs, dis, A, Bb, b1, batch, pool4, cnt, N, 1, 0);

    // ---- layer 2: B -> A -> B ----
    gemm_tile<64><<<gGemm, T>>>(Bb, W2, A, N);
    gather_csr<<<gWarp, T>>>(off, srcs, dis, A, Bb, b2, batch, pool4, cnt, N, 1, 0);

    // ---- layer 3: B -> A -> B (+ fused pooling) ----
    gemm_tile<64><<<gGemm, T>>>(Bb, W3, A, N);
    gather_csr<<<gWarp, T>>>(off, srcs, dis, A, Bb, b3, batch, pool4, cnt, N, 0, 1);

    // ---- fc ----
    fc_kernel<<<B, HD>>>(pool, cnt, Wfc, bfc, out);
}

// round 9
// speedup vs baseline: 1.1716x; 1.0291x over previous
#include <cuda_runtime.h>
#include <cuda_fp16.h>

#define MAXN  100000
#define MAXE  3200000
#define HD    64
#define NG    512
#define NC    10
#define SCANB 1024
#define MAXBLK 128   // ceil(MAXN/SCANB) = 98

// ---------------- scratch (device globals) ----------------------------------
__device__ int    g_deg[MAXN];
__device__ int    g_cur[MAXN];
__device__ int    g_off[MAXN + 1];
__device__ int    g_blksum[MAXBLK];
__device__ int    g_blkoff[MAXBLK];
__device__ float  g_dis[MAXN];              // 1/sqrt(deg+1)
__device__ int    g_srcs[MAXE];             // src ids, CSR-sorted by dst
__device__ float4 g_bufA[MAXN * HD / 8];    // fp16 h (N x 64 halves = 128B/row)
__device__ float4 g_bufB[MAXN * HD / 4];    // fp32 gather output
__device__ float4 g_pool[NG * HD / 4];
__device__ float  g_cnt [NG];

// ---------------- helpers ---------------------------------------------------
__device__ __forceinline__ void red_add_v4(float4* p, float4 v) {
    asm volatile("red.global.add.v4.f32 [%0], {%1,%2,%3,%4};"
                 :: "l"(p), "f"(v.x), "f"(v.y), "f"(v.z), "f"(v.w)
                 : "memory");
}

// ---------------- CSR build --------------------------------------------------
__global__ void deg_count(const int* __restrict__ dst, int* __restrict__ deg,
                          int E) {
    int e = blockIdx.x * blockDim.x + threadIdx.x;
    if (e < E) atomicAdd(&deg[dst[e]], 1);
}

__global__ void node_norms(const int* __restrict__ deg, float* __restrict__ dis,
                           int N) {
    int i = blockIdx.x * blockDim.x + threadIdx.x;
    if (i < N) dis[i] = rsqrtf((float)deg[i] + 1.0f);
}

// ---- 3-phase parallel exclusive scan of deg[0..N) into off[0..N] ----
__global__ void scan_p1_reduce(const int* __restrict__ deg,
                               int* __restrict__ blksum, int N) {
    __shared__ int ws[32];
    int i = blockIdx.x * SCANB + threadIdx.x;
    int v = (i < N) ? deg[i] : 0;
    int lane = threadIdx.x & 31, wid = threadIdx.x >> 5;
#pragma unroll
    for (int o = 16; o > 0; o >>= 1) v += __shfl_down_sync(~0u, v, o);
    if (lane == 0) ws[wid] = v;
    __syncthreads();
    if (wid == 0) {
        int t = ws[lane];
#pragma unroll
        for (int o = 16; o > 0; o >>= 1) t += __shfl_down_sync(~0u, t, o);
        if (lane == 0) blksum[blockIdx.x] = t;
    }
}

__global__ void scan_p2_blk(const int* __restrict__ blksum,
                            int* __restrict__ blkoff,
                            int* __restrict__ off, int nblk, int N) {
    __shared__ int s[MAXBLK];
    int t = threadIdx.x;                        // MAXBLK threads
    s[t] = (t < nblk) ? blksum[t] : 0;
    __syncthreads();
#pragma unroll
    for (int o = 1; o < MAXBLK; o <<= 1) {      // Hillis-Steele inclusive
        int v = (t >= o) ? s[t - o] : 0;
        __syncthreads();
        s[t] += v;
        __syncthreads();
    }
    if (t < nblk) blkoff[t] = s[t] - blksum[t]; // exclusive
    if (t == nblk - 1) off[N] = s[t];           // total
}

// writes both off[] and cur[] (cur consumed/destroyed by permute)
__global__ void scan_p3_scanadd(const int* __restrict__ deg,
                                const int* __restrict__ blkoff,
                                int* __restrict__ off,
                                int* __restrict__ cur, int N) {
    __shared__ int wpre[32];
    int i = blockIdx.x * SCANB + threadIdx.x;
    int v = (i < N) ? deg[i] : 0;
    int lane = threadIdx.x & 31, wid = threadIdx.x >> 5;
    int incl = v;
#pragma unroll
    for (int o = 1; o < 32; o <<= 1) {
        int t = __shfl_up_sync(~0u, incl, o);
        if (lane >= o) incl += t;
    }
    if (lane == 31) wpre[wid] = incl;
    __syncthreads();
    if (wid == 0) {
        int w = wpre[lane];
        int wincl = w;
#pragma unroll
        for (int o = 1; o < 32; o <<= 1) {
            int t = __shfl_up_sync(~0u, wincl, o);
            if (lane >= o) wincl += t;
        }
        wpre[lane] = wincl - w;
    }
    __syncthreads();
    if (i < N) {
        int o = blkoff[blockIdx.x] + wpre[wid] + incl - v;
        off[i] = o;
        cur[i] = o;
    }
}

// cur[] preloaded with off[]; atomic return carries the base directly.
__global__ void permute_edges(const int* __restrict__ src,
                              const int* __restrict__ dst,
                              int* __restrict__ cur,
                              int* __restrict__ srcs, int E) {
    int e = blockIdx.x * blockDim.x + threadIdx.x;
    if (e >= E) return;
    int s = src[e], d = dst[e];
    int p = atomicAdd(&cur[d], 1);
    srcs[p] = s;
}

// ---------------- GEMM: out[N,64](fp16) = in[N,K](fp32) @ W[K,64] -----------
template <int K>
__global__ __launch_bounds__(256)
void gemm_tile(const float* __restrict__ in, const float* __restrict__ W,
               __half* __restrict__ out, int N) {
    __shared__ float sx[64 * 36];
    __shared__ float sw[32 * 64];
    int tid = threadIdx.x;
    int tx = tid & 15, ty = tid >> 4;
    int row0 = blockIdx.x * 64;
    float acc[4][4] = {};
    for (int kc = 0; kc < K; kc += 32) {
#pragma unroll
        for (int i = 0; i < 2; i++) {
            int t = tid + i * 256;
            int r = t >> 3, c4 = t & 7;
            int grow = row0 + r;
            float4 v = make_float4(0.f, 0.f, 0.f, 0.f);
            if (grow < N)
                v = *(const float4*)&in[(size_t)grow * K + kc + c4 * 4];
            *(float4*)&sx[r * 36 + c4 * 4] = v;
        }
#pragma unroll
        for (int i = 0; i < 2; i++) {
            int t = tid + i * 256;
            int k = t >> 4, c4 = t & 15;
            *(float4*)&sw[k * 64 + c4 * 4] =
                *(const float4*)&W[(size_t)(kc + k) * 64 + c4 * 4];
        }
        __syncthreads();
#pragma unroll
        for (int k = 0; k < 32; k++) {
            float4 b = *(float4*)&sw[k * 64 + tx * 4];
            float a0 = sx[(ty * 4 + 0) * 36 + k];
            float a1 = sx[(ty * 4 + 1) * 36 + k];
            float a2 = sx[(ty * 4 + 2) * 36 + k];
            float a3 = sx[(ty * 4 + 3) * 36 + k];
            acc[0][0] = fmaf(a0, b.x, acc[0][0]);
            acc[0][1] = fmaf(a0, b.y, acc[0][1]);
            acc[0][2] = fmaf(a0, b.z, acc[0][2]);
            acc[0][3] = fmaf(a0, b.w, acc[0][3]);
            acc[1][0] = fmaf(a1, b.x, acc[1][0]);
            acc[1][1] = fmaf(a1, b.y, acc[1][1]);
            acc[1][2] = fmaf(a1, b.z, acc[1][2]);
            acc[1][3] = fmaf(a1, b.w, acc[1][3]);
            acc[2][0] = fmaf(a2, b.x, acc[2][0]);
            acc[2][1] = fmaf(a2, b.y, acc[2][1]);
            acc[2][2] = fmaf(a2, b.z, acc[2][2]);
            acc[2][3] = fmaf(a2, b.w, acc[2][3]);
            acc[3][0] = fmaf(a3, b.x, acc[3][0]);
            acc[3][1] = fmaf(a3, b.y, acc[3][1]);
            acc[3][2] = fmaf(a3, b.z, acc[3][2]);
            acc[3][3] = fmaf(a3, b.w, acc[3][3]);
        }
        __syncthreads();
    }
#pragma unroll
    for (int i = 0; i < 4; i++) {
        int grow = row0 + ty * 4 + i;
        if (grow < N) {
            __half2 h01 = __floats2half2_rn(acc[i][0], acc[i][1]);
            __half2 h23 = __floats2half2_rn(acc[i][2], acc[i][3]);
            uint2 pk = make_uint2(*(unsigned*)&h01, *(unsigned*)&h23);
            *(uint2*)&out[(size_t)grow * 64 + tx * 4] = pk;
        }
    }
}

// ---------------- fused CSR gather (fp16 in) + self-loop + bias + relu (+pool)
// one warp per dst node; two 16-lane halves each own one edge; lane owns
// 4 consecutive feature columns (4 halves = 8B in, float4 out).
__global__ __launch_bounds__(256)
void gather_csr(const int* __restrict__ off, const int* __restrict__ srcs,
                const float* __restrict__ dis, const __half* __restrict__ hin,
                float* __restrict__ hout, const float* __restrict__ bias,
                const int* __restrict__ batch, float4* __restrict__ pool4,
                float* __restrict__ cnt, int N, int do_relu, int do_pool) {
    int w = (blockIdx.x * blockDim.x + threadIdx.x) >> 5;
    int lane = threadIdx.x & 31;
    if (w >= N) return;
    int half = lane >> 4;
    int l16  = lane & 15;
    const uint2* h16 = (const uint2*)hin;       // 16 x 8B chunks per 64-half row
    int s = off[w], e = off[w + 1];
    float dw = dis[w];
    float4 acc = make_float4(0.f, 0.f, 0.f, 0.f);
    int i = s + half;
    for (; i + 2 < e; i += 4) {                 // 2 edges per half per iter
        int u0 = __ldg(&srcs[i]);
        int u1 = __ldg(&srcs[i + 2]);
        float n0 = __ldg(&dis[u0]) * dw;
        float n1 = __ldg(&dis[u1]) * dw;
        uint2 r0 = h16[(size_t)u0 * 16 + l16];
        uint2 r1 = h16[(size_t)u1 * 16 + l16];
        float2 a0 = __half22float2(*(__half2*)&r0.x);
        float2 b0 = __half22float2(*(__half2*)&r0.y);
        float2 a1 = __half22float2(*(__half2*)&r1.x);
        float2 b1 = __half22float2(*(__half2*)&r1.y);
        acc.x = fmaf(a0.x, n0, acc.x); acc.y = fmaf(a0.y, n0, acc.y);
        acc.z = fmaf(b0.x, n0, acc.z); acc.w = fmaf(b0.y, n0, acc.w);
        acc.x = fmaf(a1.x, n1, acc.x); acc.y = fmaf(a1.y, n1, acc.y);
        acc.z = fmaf(b1.x, n1, acc.z); acc.w = fmaf(b1.y, n1, acc.w);
    }
    for (; i < e; i += 2) {                     // at most one per half
        int u = __ldg(&srcs[i]);
        float n = __ldg(&dis[u]) * dw;
        uint2 r = h16[(size_t)u * 16 + l16];
        float2 a = __half22float2(*(__half2*)&r.x);
        float2 b = __half22float2(*(__half2*)&r.y);
        acc.x = fmaf(a.x, n, acc.x); acc.y = fmaf(a.y, n, acc.y);
        acc.z = fmaf(b.x, n, acc.z); acc.w = fmaf(b.y, n, acc.w);
    }
    acc.x += __shfl_down_sync(~0u, acc.x, 16);
    acc.y += __shfl_down_sync(~0u, acc.y, 16);
    acc.z += __shfl_down_sync(~0u, acc.z, 16);
    acc.w += __shfl_down_sync(~0u, acc.w, 16);
    if (half == 0) {
        float sn = dw * dw;
        uint2 sr = h16[(size_t)w * 16 + l16];
        float2 sa = __half22float2(*(__half2*)&sr.x);
        float2 sb = __half22float2(*(__half2*)&sr.y);
        float4 b = ((const float4*)bias)[l16];
        acc.x = fmaf(sa.x, sn, acc.x) + b.x;
        acc.y = fmaf(sa.y, sn, acc.y) + b.y;
        acc.z = fmaf(sb.x, sn, acc.z) + b.z;
        acc.w = fmaf(sb.y, sn, acc.w) + b.w;
        if (do_relu) {
            acc.x = fmaxf(acc.x, 0.f); acc.y = fmaxf(acc.y, 0.f);
            acc.z = fmaxf(acc.z, 0.f); acc.w = fmaxf(acc.w, 0.f);
        }
        ((float4*)hout)[(size_t)w * 16 + l16] = acc;
        if (do_pool) {
            int g = batch[w];
            red_add_v4(&pool4[(size_t)g * 16 + l16], acc);
            if (l16 == 0) atomicAdd(&cnt[g], 1.0f);
        }
    }
}

// ---------------- FC -----------------------------------------------------
__global__ void fc_kernel(const float* __restrict__ pool,
                          const float* __restrict__ cnt,
                          const float* __restrict__ Wfc,
                          const float* __restrict__ bfc,
                          float* __restrict__ out) {
    int b = blockIdx.x;
    int t = threadIdx.x;           // 64 threads
    __shared__ float p[HD];
    float inv = 1.0f / fmaxf(cnt[b], 1.0f);
    p[t] = pool[b * HD + t] * inv;
    __syncthreads();
    if (t < NC) {
        float acc = bfc[t];
#pragma unroll
        for (int h = 0; h < HD; h++)
            acc = fmaf(p[h], Wfc[h * NC + t], acc);
        out[b * NC + t] = acc;
    }
}

// ---------------- launch -----------------------------------------------------
extern "C" void kernel_launch(void* const* d_in, const int* in_sizes, int n_in,
                              void* d_out, int out_size) {
    const float* x     = (const float*)d_in[0];
    const int*   ei    = (const int*)d_in[1];     // int32 (JAX x64 disabled)
    const int*   batch = (const int*)d_in[2];
    const float* W1    = (const float*)d_in[3];
    const float* b1    = (const float*)d_in[4];
    const float* W2    = (const float*)d_in[5];
    const float* b2    = (const float*)d_in[6];
    const float* W3    = (const float*)d_in[7];
    const float* b3    = (const float*)d_in[8];
    const float* Wfc   = (const float*)d_in[9];
    const float* bfc   = (const float*)d_in[10];
    float*       out   = (float*)d_out;

    int N = in_sizes[0] / 128;
    int E = in_sizes[1] / 2;
    int B = out_size / NC;

    const int* src = ei;
    const int* dst = ei + E;

    void *p_deg, *p_cur, *p_off, *p_bs, *p_bo, *p_dis, *p_srcs,
         *p_A, *p_B, *p_pool, *p_cnt;
    cudaGetSymbolAddress(&p_deg, g_deg);
    cudaGetSymbolAddress(&p_cur, g_cur);
    cudaGetSymbolAddress(&p_off, g_off);
    cudaGetSymbolAddress(&p_bs, g_blksum);
    cudaGetSymbolAddress(&p_bo, g_blkoff);
    cudaGetSymbolAddress(&p_dis, g_dis);
    cudaGetSymbolAddress(&p_srcs, g_srcs);
    cudaGetSymbolAddress(&p_A, g_bufA);
    cudaGetSymbolAddress(&p_B, g_bufB);
    cudaGetSymbolAddress(&p_pool, g_pool);
    cudaGetSymbolAddress(&p_cnt, g_cnt);

    int*    deg   = (int*)p_deg;
    int*    cur   = (int*)p_cur;
    int*    off   = (int*)p_off;
    int*    blks  = (int*)p_bs;
    int*    blko  = (int*)p_bo;
    float*  dis   = (float*)p_dis;
    int*    srcs  = (int*)p_srcs;
    __half* A     = (__half*)p_A;               // fp16 h
    float*  Bb    = (float*)p_B;                // fp32 gather output
    float4* pool4 = (float4*)p_pool;
    float*  pool  = (float*)p_pool;
    float*  cnt   = (float*)p_cnt;

    const int T = 256;
    int gEdge = (E + T - 1) / T;
    int gNode = (N + T - 1) / T;
    int gWarp = (int)(((long long)N * 32 + T - 1) / T);
    int gGemm = (N + 63) / 64;
    int nblk  = (N + SCANB - 1) / SCANB;

    // lazily-created side stream + fork/join events (host-side handles only)
    static cudaStream_t s_side = nullptr;
    static cudaEvent_t  ev_fork = nullptr, ev_join = nullptr;
    if (s_side == nullptr) {
        cudaStreamCreateWithFlags(&s_side, cudaStreamNonBlocking);
        cudaEventCreateWithFlags(&ev_fork, cudaEventDisableTiming);
        cudaEventCreateWithFlags(&ev_join, cudaEventDisableTiming);
    }

    // ---- fork: CSR build chain on side stream, GEMM1 on main stream ----
    cudaEventRecord(ev_fork, 0);
    cudaStreamWaitEvent(s_side, ev_fork, 0);

    cudaMemsetAsync(deg, 0, (size_t)N * sizeof(int), s_side);
    deg_count<<<gEdge, T, 0, s_side>>>(dst, deg, E);
    node_norms<<<gNode, T, 0, s_side>>>(deg, dis, N);
    scan_p1_reduce<<<nblk, SCANB, 0, s_side>>>(deg, blks, N);
    scan_p2_blk<<<1, MAXBLK, 0, s_side>>>(blks, blko, off, nblk, N);
    scan_p3_scanadd<<<nblk, SCANB, 0, s_side>>>(deg, blko, off, cur, N);
    permute_edges<<<gEdge, T, 0, s_side>>>(src, dst, cur, srcs, E);
    cudaMemsetAsync(pool4, 0, (size_t)B * HD * sizeof(float), s_side);
    cudaMemsetAsync(cnt, 0, (size_t)B * sizeof(float), s_side);
    cudaEventRecord(ev_join, s_side);

    // main stream: layer-1 GEMM overlaps the CSR build
    gemm_tile<128><<<gGemm, T>>>(x, W1, A, N);

    // join before first gather
    cudaStreamWaitEvent(0, ev_join, 0);

    // ---- layer 1 gather ----
    gather_csr<<<gWarp, T>>>(off, srcs, dis, A, Bb, b1, batch, pool4, cnt, N, 1, 0);

    // ---- layer 2: B -> A -> B ----
    gemm_tile<64><<<gGemm, T>>>(Bb, W2, A, N);
    gather_csr<<<gWarp, T>>>(off, srcs, dis, A, Bb, b2, batch, pool4, cnt, N, 1, 0);

    // ---- layer 3: B -> A -> B (+ fused pooling) ----
    gemm_tile<64><<<gGemm, T>>>(Bb, W3, A, N);
    gather_csr<<<gWarp, T>>>(off, srcs, dis, A, Bb, b3, batch, pool4, cnt, N, 0, 1);

    // ---- fc ----
    fc_kernel<<<B, HD>>>(pool, cnt, Wfc, bfc, out);
}

// round 10
// speedup vs baseline: 1.2060x; 1.0293x over previous
#include <cuda_runtime.h>
#include <cuda_fp16.h>

#define MAXN  100000
#define MAXE  3200000
#define HD    64
#define NG    512
#define NC    10
#define SCANB 1024
#define MAXBLK 128   // ceil(MAXN/SCANB) = 98

// ---------------- scratch (device globals) ----------------------------------
__device__ int    g_deg[MAXN];
__device__ int    g_cur[MAXN];
__device__ int    g_off[MAXN + 1];
__device__ int    g_blksum[MAXBLK];
__device__ int    g_blkoff[MAXBLK];
__device__ float  g_dis[MAXN];              // 1/sqrt(deg+1)
__device__ int    g_srcs[MAXE];             // src ids, CSR-sorted by dst
__device__ float4 g_bufA[MAXN * HD / 8];    // fp16 h (GEMM out)
__device__ float4 g_bufB[MAXN * HD / 8];    // fp16 gather out
__device__ float4 g_pool[NG * HD / 4];
__device__ float  g_cnt [NG];

// ---------------- helpers ---------------------------------------------------
__device__ __forceinline__ void red_add_v4(float4* p, float4 v) {
    asm volatile("red.global.add.v4.f32 [%0], {%1,%2,%3,%4};"
                 :: "l"(p), "f"(v.x), "f"(v.y), "f"(v.z), "f"(v.w)
                 : "memory");
}

// ---------------- CSR build --------------------------------------------------
__global__ void deg_count(const int* __restrict__ dst, int* __restrict__ deg,
                          int E) {
    int e = blockIdx.x * blockDim.x + threadIdx.x;
    if (e < E) atomicAdd(&deg[dst[e]], 1);
}

// ---- 3-phase parallel exclusive scan of deg[0..N) into off[0..N] ----
__global__ void scan_p1_reduce(const int* __restrict__ deg,
                               int* __restrict__ blksum, int N) {
    __shared__ int ws[32];
    int i = blockIdx.x * SCANB + threadIdx.x;
    int v = (i < N) ? deg[i] : 0;
    int lane = threadIdx.x & 31, wid = threadIdx.x >> 5;
#pragma unroll
    for (int o = 16; o > 0; o >>= 1) v += __shfl_down_sync(~0u, v, o);
    if (lane == 0) ws[wid] = v;
    __syncthreads();
    if (wid == 0) {
        int t = ws[lane];
#pragma unroll
        for (int o = 16; o > 0; o >>= 1) t += __shfl_down_sync(~0u, t, o);
        if (lane == 0) blksum[blockIdx.x] = t;
    }
}

__global__ void scan_p2_blk(const int* __restrict__ blksum,
                            int* __restrict__ blkoff,
                            int* __restrict__ off, int nblk, int N) {
    __shared__ int s[MAXBLK];
    int t = threadIdx.x;                        // MAXBLK threads
    s[t] = (t < nblk) ? blksum[t] : 0;
    __syncthreads();
#pragma unroll
    for (int o = 1; o < MAXBLK; o <<= 1) {      // Hillis-Steele inclusive
        int v = (t >= o) ? s[t - o] : 0;
        __syncthreads();
        s[t] += v;
        __syncthreads();
    }
    if (t < nblk) blkoff[t] = s[t] - blksum[t]; // exclusive
    if (t == nblk - 1) off[N] = s[t];           // total
}

// writes off[], cur[], and dis[] (norms fused; cur destroyed by permute)
__global__ void scan_p3_scanadd(const int* __restrict__ deg,
                                const int* __restrict__ blkoff,
                                int* __restrict__ off,
                                int* __restrict__ cur,
                                float* __restrict__ dis, int N) {
    __shared__ int wpre[32];
    int i = blockIdx.x * SCANB + threadIdx.x;
    int v = (i < N) ? deg[i] : 0;
    int lane = threadIdx.x & 31, wid = threadIdx.x >> 5;
    int incl = v;
#pragma unroll
    for (int o = 1; o < 32; o <<= 1) {
        int t = __shfl_up_sync(~0u, incl, o);
        if (lane >= o) incl += t;
    }
    if (lane == 31) wpre[wid] = incl;
    __syncthreads();
    if (wid == 0) {
        int w = wpre[lane];
        int wincl = w;
#pragma unroll
        for (int o = 1; o < 32; o <<= 1) {
            int t = __shfl_up_sync(~0u, wincl, o);
            if (lane >= o) wincl += t;
        }
        wpre[lane] = wincl - w;
    }
    __syncthreads();
    if (i < N) {
        int o = blkoff[blockIdx.x] + wpre[wid] + incl - v;
        off[i] = o;
        cur[i] = o;
        dis[i] = rsqrtf((float)v + 1.0f);
    }
}

// cur[] preloaded with off[]; atomic return carries the base directly.
__global__ void permute_edges(const int* __restrict__ src,
                              const int* __restrict__ dst,
                              int* __restrict__ cur,
                              int* __restrict__ srcs, int E) {
    int e = blockIdx.x * blockDim.x + threadIdx.x;
    if (e >= E) return;
    int s = src[e], d = dst[e];
    int p = atomicAdd(&cur[d], 1);
    srcs[p] = s;
}

// ---------------- GEMM: out[N,64](fp16) = in[N,K] @ W[K,64] -----------------
// InT = float (layer 1) or __half (layers 2/3)
template <int K, typename InT>
__global__ __launch_bounds__(256)
void gemm_tile(const InT* __restrict__ in, const float* __restrict__ W,
               __half* __restrict__ out, int N) {
    __shared__ float sx[64 * 36];
    __shared__ float sw[32 * 64];
    int tid = threadIdx.x;
    int tx = tid & 15, ty = tid >> 4;
    int row0 = blockIdx.x * 64;
    float acc[4][4] = {};
    for (int kc = 0; kc < K; kc += 32) {
        if constexpr (sizeof(InT) == 2) {       // fp16 input: 64 rows x 32 halves
            int r = tid >> 2, c8 = tid & 3;     // 4 threads/row, 8 halves each
            int grow = row0 + r;
            uint4 v = make_uint4(0u, 0u, 0u, 0u);
            if (grow < N)
                v = *(const uint4*)&in[(size_t)grow * K + kc + c8 * 8];
            float2 f0 = __half22float2(*(__half2*)&v.x);
            float2 f1 = __half22float2(*(__half2*)&v.y);
            float2 f2 = __half22float2(*(__half2*)&v.z);
            float2 f3 = __half22float2(*(__half2*)&v.w);
            float* dstp = &sx[r * 36 + c8 * 8];
            *(float4*)&dstp[0] = make_float4(f0.x, f0.y, f1.x, f1.y);
            *(float4*)&dstp[4] = make_float4(f2.x, f2.y, f3.x, f3.y);
        } else {                                // fp32 input
#pragma unroll
            for (int i = 0; i < 2; i++) {
                int t = tid + i * 256;
                int r = t >> 3, c4 = t & 7;
                int grow = row0 + r;
                float4 v = make_float4(0.f, 0.f, 0.f, 0.f);
                if (grow < N)
                    v = *(const float4*)&((const float*)in)[(size_t)grow * K + kc + c4 * 4];
                *(float4*)&sx[r * 36 + c4 * 4] = v;
            }
        }
#pragma unroll
        for (int i = 0; i < 2; i++) {
            int t = tid + i * 256;
            int k = t >> 4, c4 = t & 15;
            *(float4*)&sw[k * 64 + c4 * 4] =
                *(const float4*)&W[(size_t)(kc + k) * 64 + c4 * 4];
        }
        __syncthreads();
#pragma unroll
        for (int k = 0; k < 32; k++) {
            float4 b = *(float4*)&sw[k * 64 + tx * 4];
            float a0 = sx[(ty * 4 + 0) * 36 + k];
            float a1 = sx[(ty * 4 + 1) * 36 + k];
            float a2 = sx[(ty * 4 + 2) * 36 + k];
            float a3 = sx[(ty * 4 + 3) * 36 + k];
            acc[0][0] = fmaf(a0, b.x, acc[0][0]);
            acc[0][1] = fmaf(a0, b.y, acc[0][1]);
            acc[0][2] = fmaf(a0, b.z, acc[0][2]);
            acc[0][3] = fmaf(a0, b.w, acc[0][3]);
            acc[1][0] = fmaf(a1, b.x, acc[1][0]);
            acc[1][1] = fmaf(a1, b.y, acc[1][1]);
            acc[1][2] = fmaf(a1, b.z, acc[1][2]);
            acc[1][3] = fmaf(a1, b.w, acc[1][3]);
            acc[2][0] = fmaf(a2, b.x, acc[2][0]);
            acc[2][1] = fmaf(a2, b.y, acc[2][1]);
            acc[2][2] = fmaf(a2, b.z, acc[2][2]);
            acc[2][3] = fmaf(a2, b.w, acc[2][3]);
            acc[3][0] = fmaf(a3, b.x, acc[3][0]);
            acc[3][1] = fmaf(a3, b.y, acc[3][1]);
            acc[3][2] = fmaf(a3, b.z, acc[3][2]);
            acc[3][3] = fmaf(a3, b.w, acc[3][3]);
        }
        __syncthreads();
    }
#pragma unroll
    for (int i = 0; i < 4; i++) {
        int grow = row0 + ty * 4 + i;
        if (grow < N) {
            __half2 h01 = __floats2half2_rn(acc[i][0], acc[i][1]);
            __half2 h23 = __floats2half2_rn(acc[i][2], acc[i][3]);
            uint2 pk = make_uint2(*(unsigned*)&h01, *(unsigned*)&h23);
            *(uint2*)&out[(size_t)grow * 64 + tx * 4] = pk;
        }
    }
}

// ---------------- fused CSR gather (fp16 in/out) + self-loop + bias + relu ---
// one warp per dst node; two 16-lane halves, 4 edges in flight per half.
__global__ __launch_bounds__(256)
void gather_csr(const int* __restrict__ off, const int* __restrict__ srcs,
                const float* __restrict__ dis, const __half* __restrict__ hin,
                __half* __restrict__ hout, const float* __restrict__ bias,
                const int* __restrict__ batch, float4* __restrict__ pool4,
                float* __restrict__ cnt, int N, int do_relu, int do_pool) {
    int w = (blockIdx.x * blockDim.x + threadIdx.x) >> 5;
    int lane = threadIdx.x & 31;
    if (w >= N) return;
    int half = lane >> 4;
    int l16  = lane & 15;
    const uint2* h16 = (const uint2*)hin;       // 16 x 8B chunks per row
    int s = off[w], e = off[w + 1];
    float dw = dis[w];
    float4 acc = make_float4(0.f, 0.f, 0.f, 0.f);
    int i = s + half;
    for (; i + 6 < e; i += 8) {                 // 4 edges per half per iter
        int u0 = __ldg(&srcs[i]);
        int u1 = __ldg(&srcs[i + 2]);
        int u2 = __ldg(&srcs[i + 4]);
        int u3 = __ldg(&srcs[i + 6]);
        float n0 = __ldg(&dis[u0]) * dw;
        float n1 = __ldg(&dis[u1]) * dw;
        float n2 = __ldg(&dis[u2]) * dw;
        float n3 = __ldg(&dis[u3]) * dw;
        uint2 r0 = h16[(size_t)u0 * 16 + l16];
        uint2 r1 = h16[(size_t)u1 * 16 + l16];
        uint2 r2 = h16[(size_t)u2 * 16 + l16];
        uint2 r3 = h16[(size_t)u3 * 16 + l16];
        float2 a0 = __half22float2(*(__half2*)&r0.x);
        float2 b0 = __half22float2(*(__half2*)&r0.y);
        float2 a1 = __half22float2(*(__half2*)&r1.x);
        float2 b1 = __half22float2(*(__half2*)&r1.y);
        float2 a2 = __half22float2(*(__half2*)&r2.x);
        float2 b2 = __half22float2(*(__half2*)&r2.y);
        float2 a3 = __half22float2(*(__half2*)&r3.x);
        float2 b3 = __half22float2(*(__half2*)&r3.y);
        acc.x = fmaf(a0.x, n0, acc.x); acc.y = fmaf(a0.y, n0, acc.y);
        acc.z = fmaf(b0.x, n0, acc.z); acc.w = fmaf(b0.y, n0, acc.w);
        acc.x = fmaf(a1.x, n1, acc.x); acc.y = fmaf(a1.y, n1, acc.y);
        acc.z = fmaf(b1.x, n1, acc.z); acc.w = fmaf(b1.y, n1, acc.w);
        acc.x = fmaf(a2.x, n2, acc.x); acc.y = fmaf(a2.y, n2, acc.y);
        acc.z = fmaf(b2.x, n2, acc.z); acc.w = fmaf(b2.y, n2, acc.w);
        acc.x = fmaf(a3.x, n3, acc.x); acc.y = fmaf(a3.y, n3, acc.y);
        acc.z = fmaf(b3.x, n3, acc.z); acc.w = fmaf(b3.y, n3, acc.w);
    }
    for (; i < e; i += 2) {
        int u = __ldg(&srcs[i]);
        float n = __ldg(&dis[u]) * dw;
        uint2 r = h16[(size_t)u * 16 + l16];
        float2 a = __half22float2(*(__half2*)&r.x);
        float2 b = __half22float2(*(__half2*)&r.y);
        acc.x = fmaf(a.x, n, acc.x); acc.y = fmaf(a.y, n, acc.y);
        acc.z = fmaf(b.x, n, acc.z); acc.w = fmaf(b.y, n, acc.w);
    }
    acc.x += __shfl_down_sync(~0u, acc.x, 16);
    acc.y += __shfl_down_sync(~0u, acc.y, 16);
    acc.z += __shfl_down_sync(~0u, acc.z, 16);
    acc.w += __shfl_down_sync(~0u, acc.w, 16);
    if (half == 0) {
        float sn = dw * dw;
        uint2 sr = h16[(size_t)w * 16 + l16];
        float2 sa = __half22float2(*(__half2*)&sr.x);
        float2 sb = __half22float2(*(__half2*)&sr.y);
        float4 b = ((const float4*)bias)[l16];
        acc.x = fmaf(sa.x, sn, acc.x) + b.x;
        acc.y = fmaf(sa.y, sn, acc.y) + b.y;
        acc.z = fmaf(sb.x, sn, acc.z) + b.z;
        acc.w = fmaf(sb.y, sn, acc.w) + b.w;
        if (do_relu) {
            acc.x = fmaxf(acc.x, 0.f); acc.y = fmaxf(acc.y, 0.f);
            acc.z = fmaxf(acc.z, 0.f); acc.w = fmaxf(acc.w, 0.f);
        }
        if (do_pool) {                          // layer 3: only pool consumed
            int g = batch[w];
            red_add_v4(&pool4[(size_t)g * 16 + l16], acc);
            if (l16 == 0) atomicAdd(&cnt[g], 1.0f);
        } else {                                // layers 1/2: fp16 store
            __half2 h01 = __floats2half2_rn(acc.x, acc.y);
            __half2 h23 = __floats2half2_rn(acc.z, acc.w);
            uint2 pk = make_uint2(*(unsigned*)&h01, *(unsigned*)&h23);
            ((uint2*)hout)[(size_t)w * 16 + l16] = pk;
        }
    }
}

// ---------------- FC -----------------------------------------------------
__global__ void fc_kernel(const float* __restrict__ pool,
                          const float* __restrict__ cnt,
                          const float* __restrict__ Wfc,
                          const float* __restrict__ bfc,
                          float* __restrict__ out) {
    int b = blockIdx.x;
    int t = threadIdx.x;           // 64 threads
    __shared__ float p[HD];
    float inv = 1.0f / fmaxf(cnt[b], 1.0f);
    p[t] = pool[b * HD + t] * inv;
    __syncthreads();
    if (t < NC) {
        float acc = bfc[t];
#pragma unroll
        for (int h = 0; h < HD; h++)
            acc = fmaf(p[h], Wfc[h * NC + t], acc);
        out[b * NC + t] = acc;
    }
}

// ---------------- launch -----------------------------------------------------
extern "C" void kernel_launch(void* const* d_in, const int* in_sizes, int n_in,
                              void* d_out, int out_size) {
    const float* x     = (const float*)d_in[0];
    const int*   ei    = (const int*)d_in[1];     // int32 (JAX x64 disabled)
    const int*   batch = (const int*)d_in[2];
    const float* W1    = (const float*)d_in[3];
    const float* b1    = (const float*)d_in[4];
    const float* W2    = (const float*)d_in[5];
    const float* b2    = (const float*)d_in[6];
    const float* W3    = (const float*)d_in[7];
    const float* b3    = (const float*)d_in[8];
    const float* Wfc   = (const float*)d_in[9];
    const float* bfc   = (const float*)d_in[10];
    float*       out   = (float*)d_out;

    int N = in_sizes[0] / 128;
    int E = in_sizes[1] / 2;
    int B = out_size / NC;

    const int* src = ei;
    const int* dst = ei + E;

    void *p_deg, *p_cur, *p_off, *p_bs, *p_bo, *p_dis, *p_srcs,
         *p_A, *p_B, *p_pool, *p_cnt;
    cudaGetSymbolAddress(&p_deg, g_deg);
    cudaGetSymbolAddress(&p_cur, g_cur);
    cudaGetSymbolAddress(&p_off, g_off);
    cudaGetSymbolAddress(&p_bs, g_blksum);
    cudaGetSymbolAddress(&p_bo, g_blkoff);
    cudaGetSymbolAddress(&p_dis, g_dis);
    cudaGetSymbolAddress(&p_srcs, g_srcs);
    cudaGetSymbolAddress(&p_A, g_bufA);
    cudaGetSymbolAddress(&p_B, g_bufB);
    cudaGetSymbolAddress(&p_pool, g_pool);
    cudaGetSymbolAddress(&p_cnt, g_cnt);

    int*    deg   = (int*)p_deg;
    int*    cur   = (int*)p_cur;
    int*    off   = (int*)p_off;
    int*    blks  = (int*)p_bs;
    int*    blko  = (int*)p_bo;
    float*  dis   = (float*)p_dis;
    int*    srcs  = (int*)p_srcs;
    __half* A     = (__half*)p_A;               // fp16 GEMM out
    __half* Bb    = (__half*)p_B;               // fp16 gather out
    float4* pool4 = (float4*)p_pool;
    float*  pool  = (float*)p_pool;
    float*  cnt   = (float*)p_cnt;

    const int T = 256;
    int gEdge = (E + T - 1) / T;
    int gWarp = (int)(((long long)N * 32 + T - 1) / T);
    int gGemm = (N + 63) / 64;
    int nblk  = (N + SCANB - 1) / SCANB;

    // lazily-created side stream + fork/join events (host-side handles only)
    static cudaStream_t s_side = nullptr;
    static cudaEvent_t  ev_fork = nullptr, ev_join = nullptr;
    if (s_side == nullptr) {
        cudaStreamCreateWithFlags(&s_side, cudaStreamNonBlocking);
        cudaEventCreateWithFlags(&ev_fork, cudaEventDisableTiming);
        cudaEventCreateWithFlags(&ev_join, cudaEventDisableTiming);
    }

    // ---- fork: CSR build chain on side stream ----
    cudaEventRecord(ev_fork, 0);
    cudaStreamWaitEvent(s_side, ev_fork, 0);

    cudaMemsetAsync(deg, 0, (size_t)N * sizeof(int), s_side);
    deg_count<<<gEdge, T, 0, s_side>>>(dst, deg, E);
    scan_p1_reduce<<<nblk, SCANB, 0, s_side>>>(deg, blks, N);
    scan_p2_blk<<<1, MAXBLK, 0, s_side>>>(blks, blko, off, nblk, N);
    scan_p3_scanadd<<<nblk, SCANB, 0, s_side>>>(deg, blko, off, cur, dis, N);
    permute_edges<<<gEdge, T, 0, s_side>>>(src, dst, cur, srcs, E);
    cudaEventRecord(ev_join, s_side);

    // main stream: pool zeroing + layer-1 GEMM overlap the CSR build
    cudaMemsetAsync(pool4, 0, (size_t)B * HD * sizeof(float));
    cudaMemsetAsync(cnt, 0, (size_t)B * sizeof(float));
    gemm_tile<128, float><<<gGemm, T>>>(x, W1, A, N);

    // join before first gather
    cudaStreamWaitEvent(0, ev_join, 0);

    // ---- layer 1 ----
    gather_csr<<<gWarp, T>>>(off, srcs, dis, A, Bb, b1, batch, pool4, cnt, N, 1, 0);

    // ---- layer 2 ----
    gemm_tile<64, __half><<<gGemm, T>>>(Bb, W2, A, N);
    gather_csr<<<gWarp, T>>>(off, srcs, dis, A, Bb, b2, batch, pool4, cnt, N, 1, 0);

    // ---- layer 3 (pool-only epilogue) ----
    gemm_tile<64, __half><<<gGemm, T>>>(Bb, W3, A, N);
    gather_csr<<<gWarp, T>>>(off, srcs, dis, A, Bb, b3, batch, pool4, cnt, N, 0, 1);

    // ---- fc ----
    fc_kernel<<<B, HD>>>(pool, cnt, Wfc, bfc, out);
}

// round 11
// speedup vs baseline: 1.2735x; 1.0560x over previous
#include <cuda_runtime.h>
#include <cuda_fp16.h>

#define MAXN  100000
#define MAXE  3200000
#define HD    64
#define NG    512
#define NC    10
#define SCANB 1024
#define MAXBLK 128   // ceil(MAXN/SCANB) = 98

// ---------------- scratch (device globals) ----------------------------------
__device__ int    g_deg[MAXN];
__device__ int    g_cur[MAXN];
__device__ int    g_off[MAXN + 1];
__device__ int    g_blksum[MAXBLK];
__device__ int    g_blkoff[MAXBLK];
__device__ float  g_dis[MAXN];              // 1/sqrt(deg+1)
__device__ int    g_srcs[MAXE];             // src ids, CSR-sorted by dst
__device__ float4 g_bufA[MAXN * HD / 8];    // fp16 h_scaled (GEMM out, x dis[row])
__device__ float4 g_bufB[MAXN * HD / 8];    // fp16 gather out (raw h for next GEMM)
__device__ float4 g_pool[NG * HD / 4];
__device__ float  g_cnt [NG];

// ---------------- helpers ---------------------------------------------------
__device__ __forceinline__ void red_add_v4(float4* p, float4 v) {
    asm volatile("red.global.add.v4.f32 [%0], {%1,%2,%3,%4};"
                 :: "l"(p), "f"(v.x), "f"(v.y), "f"(v.z), "f"(v.w)
                 : "memory");
}

// ---------------- CSR build --------------------------------------------------
__global__ void deg_count(const int* __restrict__ dst, int* __restrict__ deg,
                          int E) {
    int e = blockIdx.x * blockDim.x + threadIdx.x;
    if (e < E) atomicAdd(&deg[dst[e]], 1);
}

// ---- 3-phase parallel exclusive scan of deg[0..N) into off[0..N] ----
__global__ void scan_p1_reduce(const int* __restrict__ deg,
                               int* __restrict__ blksum, int N) {
    __shared__ int ws[32];
    int i = blockIdx.x * SCANB + threadIdx.x;
    int v = (i < N) ? deg[i] : 0;
    int lane = threadIdx.x & 31, wid = threadIdx.x >> 5;
#pragma unroll
    for (int o = 16; o > 0; o >>= 1) v += __shfl_down_sync(~0u, v, o);
    if (lane == 0) ws[wid] = v;
    __syncthreads();
    if (wid == 0) {
        int t = ws[lane];
#pragma unroll
        for (int o = 16; o > 0; o >>= 1) t += __shfl_down_sync(~0u, t, o);
        if (lane == 0) blksum[blockIdx.x] = t;
    }
}

__global__ void scan_p2_blk(const int* __restrict__ blksum,
                            int* __restrict__ blkoff,
                            int* __restrict__ off, int nblk, int N) {
    __shared__ int s[MAXBLK];
    int t = threadIdx.x;                        // MAXBLK threads
    s[t] = (t < nblk) ? blksum[t] : 0;
    __syncthreads();
#pragma unroll
    for (int o = 1; o < MAXBLK; o <<= 1) {      // Hillis-Steele inclusive
        int v = (t >= o) ? s[t - o] : 0;
        __syncthreads();
        s[t] += v;
        __syncthreads();
    }
    if (t < nblk) blkoff[t] = s[t] - blksum[t]; // exclusive
    if (t == nblk - 1) off[N] = s[t];           // total
}

// writes off[], cur[], and dis[] (norms fused; cur destroyed by permute)
__global__ void scan_p3_scanadd(const int* __restrict__ deg,
                                const int* __restrict__ blkoff,
                                int* __restrict__ off,
                                int* __restrict__ cur,
                                float* __restrict__ dis, int N) {
    __shared__ int wpre[32];
    int i = blockIdx.x * SCANB + threadIdx.x;
    int v = (i < N) ? deg[i] : 0;
    int lane = threadIdx.x & 31, wid = threadIdx.x >> 5;
    int incl = v;
#pragma unroll
    for (int o = 1; o < 32; o <<= 1) {
        int t = __shfl_up_sync(~0u, incl, o);
        if (lane >= o) incl += t;
    }
    if (lane == 31) wpre[wid] = incl;
    __syncthreads();
    if (wid == 0) {
        int w = wpre[lane];
        int wincl = w;
#pragma unroll
        for (int o = 1; o < 32; o <<= 1) {
            int t = __shfl_up_sync(~0u, wincl, o);
            if (lane >= o) wincl += t;
        }
        wpre[lane] = wincl - w;
    }
    __syncthreads();
    if (i < N) {
        int o = blkoff[blockIdx.x] + wpre[wid] + incl - v;
        off[i] = o;
        cur[i] = o;
        dis[i] = rsqrtf((float)v + 1.0f);
    }
}

// cur[] preloaded with off[]; atomic return carries the base directly.
__global__ void permute_edges(const int* __restrict__ src,
                              const int* __restrict__ dst,
                              int* __restrict__ cur,
                              int* __restrict__ srcs, int E) {
    int e = blockIdx.x * blockDim.x + threadIdx.x;
    if (e >= E) return;
    int s = src[e], d = dst[e];
    int p = atomicAdd(&cur[d], 1);
    srcs[p] = s;
}

// ------- GEMM: out[N,64](fp16) = (in[N,K] @ W[K,64]) * dis[row] -------------
// InT = float (layer 1) or __half (layers 2/3)
template <int K, typename InT>
__global__ __launch_bounds__(256)
void gemm_tile(const InT* __restrict__ in, const float* __restrict__ W,
               const float* __restrict__ dis, __half* __restrict__ out, int N) {
    __shared__ float sx[64 * 36];
    __shared__ float sw[32 * 64];
    int tid = threadIdx.x;
    int tx = tid & 15, ty = tid >> 4;
    int row0 = blockIdx.x * 64;
    float acc[4][4] = {};
    for (int kc = 0; kc < K; kc += 32) {
        if constexpr (sizeof(InT) == 2) {       // fp16 input: 64 rows x 32 halves
            int r = tid >> 2, c8 = tid & 3;     // 4 threads/row, 8 halves each
            int grow = row0 + r;
            uint4 v = make_uint4(0u, 0u, 0u, 0u);
            if (grow < N)
                v = *(const uint4*)&in[(size_t)grow * K + kc + c8 * 8];
            float2 f0 = __half22float2(*(__half2*)&v.x);
            float2 f1 = __half22float2(*(__half2*)&v.y);
            float2 f2 = __half22float2(*(__half2*)&v.z);
            float2 f3 = __half22float2(*(__half2*)&v.w);
            float* dstp = &sx[r * 36 + c8 * 8];
            *(float4*)&dstp[0] = make_float4(f0.x, f0.y, f1.x, f1.y);
            *(float4*)&dstp[4] = make_float4(f2.x, f2.y, f3.x, f3.y);
        } else {                                // fp32 input
#pragma unroll
            for (int i = 0; i < 2; i++) {
                int t = tid + i * 256;
                int r = t >> 3, c4 = t & 7;
                int grow = row0 + r;
                float4 v = make_float4(0.f, 0.f, 0.f, 0.f);
                if (grow < N)
                    v = *(const float4*)&((const float*)in)[(size_t)grow * K + kc + c4 * 4];
                *(float4*)&sx[r * 36 + c4 * 4] = v;
            }
        }
#pragma unroll
        for (int i = 0; i < 2; i++) {
            int t = tid + i * 256;
            int k = t >> 4, c4 = t & 15;
            *(float4*)&sw[k * 64 + c4 * 4] =
                *(const float4*)&W[(size_t)(kc + k) * 64 + c4 * 4];
        }
        __syncthreads();
#pragma unroll
        for (int k = 0; k < 32; k++) {
            float4 b = *(float4*)&sw[k * 64 + tx * 4];
            float a0 = sx[(ty * 4 + 0) * 36 + k];
            float a1 = sx[(ty * 4 + 1) * 36 + k];
            float a2 = sx[(ty * 4 + 2) * 36 + k];
            float a3 = sx[(ty * 4 + 3) * 36 + k];
            acc[0][0] = fmaf(a0, b.x, acc[0][0]);
            acc[0][1] = fmaf(a0, b.y, acc[0][1]);
            acc[0][2] = fmaf(a0, b.z, acc[0][2]);
            acc[0][3] = fmaf(a0, b.w, acc[0][3]);
            acc[1][0] = fmaf(a1, b.x, acc[1][0]);
            acc[1][1] = fmaf(a1, b.y, acc[1][1]);
            acc[1][2] = fmaf(a1, b.z, acc[1][2]);
            acc[1][3] = fmaf(a1, b.w, acc[1][3]);
            acc[2][0] = fmaf(a2, b.x, acc[2][0]);
            acc[2][1] = fmaf(a2, b.y, acc[2][1]);
            acc[2][2] = fmaf(a2, b.z, acc[2][2]);
            acc[2][3] = fmaf(a2, b.w, acc[2][3]);
            acc[3][0] = fmaf(a3, b.x, acc[3][0]);
            acc[3][1] = fmaf(a3, b.y, acc[3][1]);
            acc[3][2] = fmaf(a3, b.z, acc[3][2]);
            acc[3][3] = fmaf(a3, b.w, acc[3][3]);
        }
        __syncthreads();
    }
#pragma unroll
    for (int i = 0; i < 4; i++) {
        int grow = row0 + ty * 4 + i;
        if (grow < N) {
            float dsc = __ldg(&dis[grow]);      // pre-scale row by dis[row]
            __half2 h01 = __floats2half2_rn(acc[i][0] * dsc, acc[i][1] * dsc);
            __half2 h23 = __floats2half2_rn(acc[i][2] * dsc, acc[i][3] * dsc);
            uint2 pk = make_uint2(*(unsigned*)&h01, *(unsigned*)&h23);
            *(uint2*)&out[(size_t)grow * 64 + tx * 4] = pk;
        }
    }
}

// ---- fused CSR gather: result[w] = dis[w]*(Σ ĥ[u] + ĥ[w]) + bias ----------
// ĥ rows are pre-scaled by dis at GEMM time: per edge = index load + row add.
__global__ __launch_bounds__(256)
void gather_csr(const int* __restrict__ off, const int* __restrict__ srcs,
                const float* __restrict__ dis, const __half* __restrict__ hin,
                __half* __restrict__ hout, const float* __restrict__ bias,
                const int* __restrict__ batch, float4* __restrict__ pool4,
                float* __restrict__ cnt, int N, int do_relu, int do_pool) {
    int w = (blockIdx.x * blockDim.x + threadIdx.x) >> 5;
    int lane = threadIdx.x & 31;
    if (w >= N) return;
    int half = lane >> 4;
    int l16  = lane & 15;
    const uint2* h16 = (const uint2*)hin;       // 16 x 8B chunks per row
    int s = off[w], e = off[w + 1];
    float4 acc = make_float4(0.f, 0.f, 0.f, 0.f);
    int i = s + half;
    for (; i + 6 < e; i += 8) {                 // 4 edges per half per iter
        int u0 = __ldg(&srcs[i]);
        int u1 = __ldg(&srcs[i + 2]);
        int u2 = __ldg(&srcs[i + 4]);
        int u3 = __ldg(&srcs[i + 6]);
        uint2 r0 = h16[(size_t)u0 * 16 + l16];
        uint2 r1 = h16[(size_t)u1 * 16 + l16];
        uint2 r2 = h16[(size_t)u2 * 16 + l16];
        uint2 r3 = h16[(size_t)u3 * 16 + l16];
        float2 a0 = __half22float2(*(__half2*)&r0.x);
        float2 b0 = __half22float2(*(__half2*)&r0.y);
        float2 a1 = __half22float2(*(__half2*)&r1.x);
        float2 b1 = __half22float2(*(__half2*)&r1.y);
        float2 a2 = __half22float2(*(__half2*)&r2.x);
        float2 b2 = __half22float2(*(__half2*)&r2.y);
        float2 a3 = __half22float2(*(__half2*)&r3.x);
        float2 b3 = __half22float2(*(__half2*)&r3.y);
        acc.x += a0.x + a1.x; acc.y += a0.y + a1.y;
        acc.z += b0.x + b1.x; acc.w += b0.y + b1.y;
        acc.x += a2.x + a3.x; acc.y += a2.y + a3.y;
        acc.z += b2.x + b3.x; acc.w += b2.y + b3.y;
    }
    for (; i < e; i += 2) {
        int u = __ldg(&srcs[i]);
        uint2 r = h16[(size_t)u * 16 + l16];
        float2 a = __half22float2(*(__half2*)&r.x);
        float2 b = __half22float2(*(__half2*)&r.y);
        acc.x += a.x; acc.y += a.y;
        acc.z += b.x; acc.w += b.y;
    }
    acc.x += __shfl_down_sync(~0u, acc.x, 16);
    acc.y += __shfl_down_sync(~0u, acc.y, 16);
    acc.z += __shfl_down_sync(~0u, acc.z, 16);
    acc.w += __shfl_down_sync(~0u, acc.w, 16);
    if (half == 0) {
        float dw = dis[w];
        uint2 sr = h16[(size_t)w * 16 + l16];   // self term: ĥ[w]
        float2 sa = __half22float2(*(__half2*)&sr.x);
        float2 sb = __half22float2(*(__half2*)&sr.y);
        float4 b = ((const float4*)bias)[l16];
        acc.x = fmaf(acc.x + sa.x, dw, b.x);
        acc.y = fmaf(acc.y + sa.y, dw, b.y);
        acc.z = fmaf(acc.z + sb.x, dw, b.z);
        acc.w = fmaf(acc.w + sb.y, dw, b.w);
        if (do_relu) {
            acc.x = fmaxf(acc.x, 0.f); acc.y = fmaxf(acc.y, 0.f);
            acc.z = fmaxf(acc.z, 0.f); acc.w = fmaxf(acc.w, 0.f);
        }
        if (do_pool) {                          // layer 3: only pool consumed
            int g = batch[w];
            red_add_v4(&pool4[(size_t)g * 16 + l16], acc);
            if (l16 == 0) atomicAdd(&cnt[g], 1.0f);
        } else {                                // layers 1/2: fp16 store (raw h)
            __half2 h01 = __floats2half2_rn(acc.x, acc.y);
            __half2 h23 = __floats2half2_rn(acc.z, acc.w);
            uint2 pk = make_uint2(*(unsigned*)&h01, *(unsigned*)&h23);
            ((uint2*)hout)[(size_t)w * 16 + l16] = pk;
        }
    }
}

// ---------------- FC -----------------------------------------------------
__global__ void fc_kernel(const float* __restrict__ pool,
                          const float* __restrict__ cnt,
                          const float* __restrict__ Wfc,
                          const float* __restrict__ bfc,
                          float* __restrict__ out) {
    int b = blockIdx.x;
    int t = threadIdx.x;           // 64 threads
    __shared__ float p[HD];
    float inv = 1.0f / fmaxf(cnt[b], 1.0f);
    p[t] = pool[b * HD + t] * inv;
    __syncthreads();
    if (t < NC) {
        float acc = bfc[t];
#pragma unroll
        for (int h = 0; h < HD; h++)
            acc = fmaf(p[h], Wfc[h * NC + t], acc);
        out[b * NC + t] = acc;
    }
}

// ---------------- launch -----------------------------------------------------
extern "C" void kernel_launch(void* const* d_in, const int* in_sizes, int n_in,
                              void* d_out, int out_size) {
    const float* x     = (const float*)d_in[0];
    const int*   ei    = (const int*)d_in[1];     // int32 (JAX x64 disabled)
    const int*   batch = (const int*)d_in[2];
    const float* W1    = (const float*)d_in[3];
    const float* b1    = (const float*)d_in[4];
    const float* W2    = (const float*)d_in[5];
    const float* b2    = (const float*)d_in[6];
    const float* W3    = (const float*)d_in[7];
    const float* b3    = (const float*)d_in[8];
    const float* Wfc   = (const float*)d_in[9];
    const float* bfc   = (const float*)d_in[10];
    float*       out   = (float*)d_out;

    int N = in_sizes[0] / 128;
    int E = in_sizes[1] / 2;
    int B = out_size / NC;

    const int* src = ei;
    const int* dst = ei + E;

    void *p_deg, *p_cur, *p_off, *p_bs, *p_bo, *p_dis, *p_srcs,
         *p_A, *p_B, *p_pool, *p_cnt;
    cudaGetSymbolAddress(&p_deg, g_deg);
    cudaGetSymbolAddress(&p_cur, g_cur);
    cudaGetSymbolAddress(&p_off, g_off);
    cudaGetSymbolAddress(&p_bs, g_blksum);
    cudaGetSymbolAddress(&p_bo, g_blkoff);
    cudaGetSymbolAddress(&p_dis, g_dis);
    cudaGetSymbolAddress(&p_srcs, g_srcs);
    cudaGetSymbolAddress(&p_A, g_bufA);
    cudaGetSymbolAddress(&p_B, g_bufB);
    cudaGetSymbolAddress(&p_pool, g_pool);
    cudaGetSymbolAddress(&p_cnt, g_cnt);

    int*    deg   = (int*)p_deg;
    int*    cur   = (int*)p_cur;
    int*    off   = (int*)p_off;
    int*    blks  = (int*)p_bs;
    int*    blko  = (int*)p_bo;
    float*  dis   = (float*)p_dis;
    int*    srcs  = (int*)p_srcs;
    __half* A     = (__half*)p_A;               // fp16 ĥ (pre-scaled)
    __half* Bb    = (__half*)p_B;               // fp16 gather out (raw h)
    float4* pool4 = (float4*)p_pool;
    float*  pool  = (float*)p_pool;
    float*  cnt   = (float*)p_cnt;

    const int T = 256;
    int gEdge = (E + T - 1) / T;
    int gWarp = (int)(((long long)N * 32 + T - 1) / T);
    int gGemm = (N + 63) / 64;
    int nblk  = (N + SCANB - 1) / SCANB;

    // lazily-created side stream + fork/join events (host-side handles only)
    static cudaStream_t s_side = nullptr;
    static cudaEvent_t  ev_fork = nullptr, ev_dis = nullptr, ev_join = nullptr;
    if (s_side == nullptr) {
        cudaStreamCreateWithFlags(&s_side, cudaStreamNonBlocking);
        cudaEventCreateWithFlags(&ev_fork, cudaEventDisableTiming);
        cudaEventCreateWithFlags(&ev_dis, cudaEventDisableTiming);
        cudaEventCreateWithFlags(&ev_join, cudaEventDisableTiming);
    }

    // ---- fork: CSR build chain on side stream ----
    cudaEventRecord(ev_fork, 0);
    cudaStreamWaitEvent(s_side, ev_fork, 0);

    cudaMemsetAsync(deg, 0, (size_t)N * sizeof(int), s_side);
    deg_count<<<gEdge, T, 0, s_side>>>(dst, deg, E);
    scan_p1_reduce<<<nblk, SCANB, 0, s_side>>>(deg, blks, N);
    scan_p2_blk<<<1, MAXBLK, 0, s_side>>>(blks, blko, off, nblk, N);
    scan_p3_scanadd<<<nblk, SCANB, 0, s_side>>>(deg, blko, off, cur, dis, N);
    cudaEventRecord(ev_dis, s_side);            // dis[] ready here
    permute_edges<<<gEdge, T, 0, s_side>>>(src, dst, cur, srcs, E);
    cudaEventRecord(ev_join, s_side);

    // main stream: pool zeroing overlaps; GEMM1 needs dis -> waits ev_dis,
    // then runs concurrently with permute on the side stream.
    cudaMemsetAsync(pool4, 0, (size_t)B * HD * sizeof(float));
    cudaMemsetAsync(cnt, 0, (size_t)B * sizeof(float));
    cudaStreamWaitEvent(0, ev_dis, 0);
    gemm_tile<128, float><<<gGemm, T>>>(x, W1, dis, A, N);

    // join before first gather
    cudaStreamWaitEvent(0, ev_join, 0);

    // ---- layer 1 ----
    gather_csr<<<gWarp, T>>>(off, srcs, dis, A, Bb, b1, batch, pool4, cnt, N, 1, 0);

    // ---- layer 2 ----
    gemm_tile<64, __half><<<gGemm, T>>>(Bb, W2, dis, A, N);
    gather_csr<<<gWarp, T>>>(off, srcs, dis, A, Bb, b2, batch, pool4, cnt, N, 1, 0);

    // ---- layer 3 (pool-only epilogue) ----
    gemm_tile<64, __half><<<gGemm, T>>>(Bb, W3, dis, A, N);
    gather_csr<<<gWarp, T>>>(off, srcs, dis, A, Bb, b3, batch, pool4, cnt, N, 0, 1);

    // ---- fc ----
    fc_kernel<<<B, HD>>>(pool, cnt, Wfc, bfc, out);
}